// round 16
// baseline (speedup 1.0000x reference)
#include <cuda_runtime.h>

#define N 512
#define KC 16
#define KQ 128                            // k-quarter per GEMM block
#define NCH (KQ / KC)                     // 8 chunks
#define NTILE 16
#define NTRI (NTILE * (NTILE + 1) / 2)    // 136 upper-triangle tiles
#define NGEMM (4 * NTRI)                  // 544 blocks (tile x k-quarter)
#define PAD 36                            // A row stride: 144B, 16B-aligned
#define PADB 68                           // B-dup row stride: 272B, 16B-aligned
#define NB2 512                           // smoothap blocks
#define NT2 256                           // smoothap threads

// Scratch (no allocations allowed).
__device__ float d_simP[4][N * N];        // split-K partials
__device__ float d_acc;
__device__ unsigned d_done;               // ticket, wraps mod NB2 per replay

// sigmoid(diff/0.01): 0.5 + 0.5*tanh(50*diff); tanh.approx saturates exactly
// where the reference's clipped sigmoid is 0/1, so the clip is free.
__device__ __forceinline__ float sig100(float diff) {
    float t;
    asm("tanh.approx.f32 %0, %1;" : "=f"(t) : "f"(50.0f * diff));
    return fmaf(0.5f, t, 0.5f);
}

// Packed fp32x2 FMA (FFMA2): 2 IEEE fp32 FMAs in one instruction.
__device__ __forceinline__ unsigned long long ffma2(unsigned long long a,
                                                    unsigned long long b,
                                                    unsigned long long c) {
    unsigned long long d;
    asm("fma.rn.f32x2 %0, %1, %2, %3;" : "=l"(d) : "l"(a), "l"(b), "l"(c));
    return d;
}
__device__ __forceinline__ float f2lo(unsigned long long v) {
    return __uint_as_float((unsigned)(v & 0xffffffffull));
}
__device__ __forceinline__ float f2hi(unsigned long long v) {
    return __uint_as_float((unsigned)(v >> 32));
}

// --- Kernel 1: split-K(x4) symmetric SGEMM via FFMA2 -----------------------
// 136 upper-triangle 32x32 tiles x 4 k-quarters = 544 blocks, 128 threads.
// Each thread: 4 rows x 2 cols, accumulated as 2x2 packed row-pairs.
// A tile k-major (row pairs load packed via LDS.64); B tile stored
// DUPLICATED ({b,b} per value) so the multiplier pair loads packed too.
__global__ __launch_bounds__(128) void gemm_sym_kernel(const float* __restrict__ P) {
    if (blockIdx.x == 0 && threadIdx.x == 0) d_acc = 0.0f;

    const int t = blockIdx.x >> 2, kq = blockIdx.x & 3, kbase = kq * KQ;
    int bi = 0, rem = t;
    #pragma unroll
    for (int r = 0; r < NTILE; r++) {
        int c = NTILE - r;
        if (rem >= c) { rem -= c; bi++; } else break;
    }
    const int bj = bi + rem;
    const int row0 = bi * 32, col0 = bj * 32;
    float* __restrict__ dst = d_simP[kq];

    __shared__ float As[2][KC][PAD];      // As[k][row]
    __shared__ float Bd[2][KC][PADB];     // Bd[k][2c..2c+1] = {b, b}
    __shared__ float Ct[32][33];

    const int tid = threadIdx.x;
    const int tx = tid & 15;          // col pair (cols 2tx, 2tx+1)
    const int ty = tid >> 4;          // row quad (rows 4ty..4ty+3)
    const int lrow = tid >> 2;        // load row 0..31
    const int lk = (tid & 3) * 4;     // load k offset

    unsigned long long acc2[2][2] = {{0ull, 0ull}, {0ull, 0ull}};

    float4 ra = *reinterpret_cast<const float4*>(&P[(row0 + lrow) * N + kbase + lk]);
    float4 rb = *reinterpret_cast<const float4*>(&P[(col0 + lrow) * N + kbase + lk]);
    As[0][lk + 0][lrow] = ra.x; As[0][lk + 1][lrow] = ra.y;
    As[0][lk + 2][lrow] = ra.z; As[0][lk + 3][lrow] = ra.w;
    Bd[0][lk + 0][2 * lrow] = rb.x; Bd[0][lk + 0][2 * lrow + 1] = rb.x;
    Bd[0][lk + 1][2 * lrow] = rb.y; Bd[0][lk + 1][2 * lrow + 1] = rb.y;
    Bd[0][lk + 2][2 * lrow] = rb.z; Bd[0][lk + 2][2 * lrow + 1] = rb.z;
    Bd[0][lk + 3][2 * lrow] = rb.w; Bd[0][lk + 3][2 * lrow + 1] = rb.w;
    __syncthreads();

    for (int c = 0; c < NCH; c++) {
        const int cur = c & 1;
        if (c + 1 < NCH) {
            const int k0 = kbase + (c + 1) * KC;
            ra = *reinterpret_cast<const float4*>(&P[(row0 + lrow) * N + k0 + lk]);
            rb = *reinterpret_cast<const float4*>(&P[(col0 + lrow) * N + k0 + lk]);
        }
        #pragma unroll
        for (int kk = 0; kk < KC; kk++) {
            const unsigned long long a01 =
                *reinterpret_cast<const unsigned long long*>(&As[cur][kk][ty * 4]);
            const unsigned long long a23 =
                *reinterpret_cast<const unsigned long long*>(&As[cur][kk][ty * 4 + 2]);
            const unsigned long long b0 =
                *reinterpret_cast<const unsigned long long*>(&Bd[cur][kk][tx * 4]);
            const unsigned long long b1 =
                *reinterpret_cast<const unsigned long long*>(&Bd[cur][kk][tx * 4 + 2]);
            acc2[0][0] = ffma2(a01, b0, acc2[0][0]);
            acc2[0][1] = ffma2(a01, b1, acc2[0][1]);
            acc2[1][0] = ffma2(a23, b0, acc2[1][0]);
            acc2[1][1] = ffma2(a23, b1, acc2[1][1]);
        }
        if (c + 1 < NCH) {
            const int nxt = cur ^ 1;
            As[nxt][lk + 0][lrow] = ra.x; As[nxt][lk + 1][lrow] = ra.y;
            As[nxt][lk + 2][lrow] = ra.z; As[nxt][lk + 3][lrow] = ra.w;
            Bd[nxt][lk + 0][2 * lrow] = rb.x; Bd[nxt][lk + 0][2 * lrow + 1] = rb.x;
            Bd[nxt][lk + 1][2 * lrow] = rb.y; Bd[nxt][lk + 1][2 * lrow + 1] = rb.y;
            Bd[nxt][lk + 2][2 * lrow] = rb.z; Bd[nxt][lk + 2][2 * lrow + 1] = rb.z;
            Bd[nxt][lk + 3][2 * lrow] = rb.w; Bd[nxt][lk + 3][2 * lrow + 1] = rb.w;
        }
        __syncthreads();
    }

    // Unpack: acc2[rp][cc] = {row 4ty+2rp (lo), row 4ty+2rp+1 (hi)} x col 2tx+cc.
    #pragma unroll
    for (int rp = 0; rp < 2; rp++) {
        float2 vlo = make_float2(f2lo(acc2[rp][0]), f2lo(acc2[rp][1]));
        float2 vhi = make_float2(f2hi(acc2[rp][0]), f2hi(acc2[rp][1]));
        *reinterpret_cast<float2*>(&dst[(row0 + ty * 4 + 2 * rp + 0) * N + col0 + tx * 2]) = vlo;
        *reinterpret_cast<float2*>(&dst[(row0 + ty * 4 + 2 * rp + 1) * N + col0 + tx * 2]) = vhi;
    }
    if (bi != bj) {                   // mirror tile via SMEM transpose
        #pragma unroll
        for (int rp = 0; rp < 2; rp++) {
            Ct[tx * 2 + 0][ty * 4 + 2 * rp + 0] = f2lo(acc2[rp][0]);
            Ct[tx * 2 + 1][ty * 4 + 2 * rp + 0] = f2lo(acc2[rp][1]);
            Ct[tx * 2 + 0][ty * 4 + 2 * rp + 1] = f2hi(acc2[rp][0]);
            Ct[tx * 2 + 1][ty * 4 + 2 * rp + 1] = f2hi(acc2[rp][1]);
        }
        __syncthreads();
        #pragma unroll
        for (int idx = tid; idx < 1024; idx += 128) {
            const int r2 = idx >> 5, c2 = idx & 31;
            dst[(col0 + r2) * N + row0 + c2] = Ct[r2][c2];
        }
    }
}

// --- Kernel 2: SmoothAP body, positives-only (proven R4 shape) -------------
// One block per anchor (512 x 256 threads); row assembled from 4 partials.
// Only ~9 of 512 j's per anchor need the k-reduction; jobs striped on warps.
__global__ __launch_bounds__(NT2) void smoothap_kernel(const int* __restrict__ labels,
                                                       float* __restrict__ out) {
    const int i = blockIdx.x;
    const int t = threadIdx.x;

    __shared__ float s[N];       // combined sim row
    __shared__ float pflag[N];   // positive mask
    __shared__ int   jlist[N];   // jlist[0] = i, then positive indices
    __shared__ int   cnt;
    __shared__ float ssum;

    if (t == 0) { cnt = 1; ssum = 0.0f; jlist[0] = i; }
    __syncthreads();

    {   // s[k] = sum of 4 split-K partials (float2-coalesced)
        const int k2 = t * 2;
        float2 v = make_float2(0.f, 0.f);
        #pragma unroll
        for (int q = 0; q < 4; q++) {
            const float2 u = *reinterpret_cast<const float2*>(&d_simP[q][i * N + k2]);
            v.x += u.x; v.y += u.y;
        }
        *reinterpret_cast<float2*>(&s[k2]) = v;
    }

    const int li = labels[i];
    #pragma unroll
    for (int k = t; k < N; k += NT2) {
        const bool p = (labels[k] == li) && (k != i);
        pflag[k] = p ? 1.0f : 0.0f;
        if (p) jlist[atomicAdd(&cnt, 1)] = k;
    }
    __syncthreads();

    const int m1 = cnt;                 // n_pos = m + 1
    const int lane = t & 31, w = t >> 5;

    for (int jj = w; jj < m1; jj += NT2 / 32) {
        const int j = jlist[jj];
        const float sj = s[j];
        float sa = 0.0f, sp = 0.0f;
        #pragma unroll
        for (int it = 0; it < N / 32; it++) {
            const int k = lane + it * 32;
            float g = sig100(s[k] - sj);
            g = (k == j) ? 0.0f : g;    // (1-eye)[j,k] mask
            sa += g;
            sp = fmaf(g, pflag[k], sp);
        }
        #pragma unroll
        for (int o = 16; o; o >>= 1) {
            sa += __shfl_xor_sync(0xFFFFFFFFu, sa, o);
            sp += __shfl_xor_sync(0xFFFFFFFFu, sp, o);
        }
        if (lane == 0) {
            const float ratio = (jj == 0) ? 1.0f / (1.0f + sa)
                                          : (1.0f + sp) / (1.0f + sa);
            atomicAdd(&ssum, ratio);
        }
    }
    __syncthreads();

    if (t == 0) {
        const float pa = (m1 > 1) ? ssum / (float)m1 : 0.0f;  // where(n_pos>1)
        atomicAdd(&d_acc, pa);
        __threadfence();
        const unsigned old = atomicInc(&d_done, NB2 - 1);     // wraps to 0
        if (old == NB2 - 1)
            out[0] = 1.0f - atomicAdd(&d_acc, 0.0f) / (float)N;
    }
}

extern "C" void kernel_launch(void* const* d_in, const int* in_sizes, int n_in,
                              void* d_out, int out_size) {
    const float* preds = (const float*)d_in[0];
    const int* labels = (const int*)d_in[1];
    float* out = (float*)d_out;

    gemm_sym_kernel<<<NGEMM, 128>>>(preds);
    smoothap_kernel<<<NB2, NT2>>>(labels, out);
}

// round 17
// speedup vs baseline: 1.3871x; 1.3871x over previous
#include <cuda_runtime.h>

#define N 512
#define KC 16
#define KQ 128                            // k-quarter per GEMM block
#define NCH (KQ / KC)                     // 8 chunks
#define NTILE 16
#define NTRI (NTILE * (NTILE + 1) / 2)    // 136 upper-triangle tiles
#define NGEMM (4 * NTRI)                  // 544 blocks (tile x k-quarter)
#define PAD 36                            // SMEM row stride: 144B, 16B-aligned
#define NB2 512                           // smoothap blocks
#define NT2 256                           // smoothap threads

// Scratch (no allocations allowed).
__device__ float d_simP[4][N * N];        // split-K partials

// sigmoid(diff/0.01): 0.5 + 0.5*tanh(50*diff); tanh.approx saturates exactly
// where the reference's clipped sigmoid is 0/1, so the clip is free.
__device__ __forceinline__ float sig100(float diff) {
    float t;
    asm("tanh.approx.f32 %0, %1;" : "=f"(t) : "f"(50.0f * diff));
    return fmaf(0.5f, t, 0.5f);
}

// --- Kernel 1: split-K(x4) symmetric SGEMM sim = P*P^T ---------------------
// 136 upper-triangle 32x32 tiles x 4 k-quarters = 544 blocks, 128 threads,
// 8 outputs/thread (4 rows x 2 cols). ~3.7 blocks/SM -> latency hidden.
// Also seeds out[0] = 1.0 (runs entirely before smoothap's REDG adds).
__global__ __launch_bounds__(128) void gemm_sym_kernel(const float* __restrict__ P,
                                                       float* __restrict__ out) {
    if (blockIdx.x == 0 && threadIdx.x == 0) out[0] = 1.0f;

    const int t = blockIdx.x >> 2, kq = blockIdx.x & 3, kbase = kq * KQ;
    int bi = 0, rem = t;
    #pragma unroll
    for (int r = 0; r < NTILE; r++) {
        int c = NTILE - r;
        if (rem >= c) { rem -= c; bi++; } else break;
    }
    const int bj = bi + rem;
    const int row0 = bi * 32, col0 = bj * 32;
    float* __restrict__ dst = d_simP[kq];

    __shared__ float As[2][KC][PAD];
    __shared__ float Bs[2][KC][PAD];
    __shared__ float Ct[32][33];

    const int tid = threadIdx.x;
    const int tx = tid & 15;          // col pair
    const int ty = tid >> 4;          // row quad
    const int lrow = tid >> 2;        // load row 0..31
    const int lk = (tid & 3) * 4;     // load k offset

    float acc[4][2];
    #pragma unroll
    for (int m = 0; m < 4; m++) { acc[m][0] = 0.f; acc[m][1] = 0.f; }

    float4 ra = *reinterpret_cast<const float4*>(&P[(row0 + lrow) * N + kbase + lk]);
    float4 rb = *reinterpret_cast<const float4*>(&P[(col0 + lrow) * N + kbase + lk]);
    As[0][lk + 0][lrow] = ra.x; As[0][lk + 1][lrow] = ra.y;
    As[0][lk + 2][lrow] = ra.z; As[0][lk + 3][lrow] = ra.w;
    Bs[0][lk + 0][lrow] = rb.x; Bs[0][lk + 1][lrow] = rb.y;
    Bs[0][lk + 2][lrow] = rb.z; Bs[0][lk + 3][lrow] = rb.w;
    __syncthreads();

    for (int c = 0; c < NCH; c++) {
        const int cur = c & 1;
        if (c + 1 < NCH) {
            const int k0 = kbase + (c + 1) * KC;
            ra = *reinterpret_cast<const float4*>(&P[(row0 + lrow) * N + k0 + lk]);
            rb = *reinterpret_cast<const float4*>(&P[(col0 + lrow) * N + k0 + lk]);
        }
        #pragma unroll
        for (int kk = 0; kk < KC; kk++) {
            const float4 a = *reinterpret_cast<const float4*>(&As[cur][kk][ty * 4]);
            const float2 bb = *reinterpret_cast<const float2*>(&Bs[cur][kk][tx * 2]);
            acc[0][0] = fmaf(a.x, bb.x, acc[0][0]); acc[0][1] = fmaf(a.x, bb.y, acc[0][1]);
            acc[1][0] = fmaf(a.y, bb.x, acc[1][0]); acc[1][1] = fmaf(a.y, bb.y, acc[1][1]);
            acc[2][0] = fmaf(a.z, bb.x, acc[2][0]); acc[2][1] = fmaf(a.z, bb.y, acc[2][1]);
            acc[3][0] = fmaf(a.w, bb.x, acc[3][0]); acc[3][1] = fmaf(a.w, bb.y, acc[3][1]);
        }
        if (c + 1 < NCH) {
            const int nxt = cur ^ 1;
            As[nxt][lk + 0][lrow] = ra.x; As[nxt][lk + 1][lrow] = ra.y;
            As[nxt][lk + 2][lrow] = ra.z; As[nxt][lk + 3][lrow] = ra.w;
            Bs[nxt][lk + 0][lrow] = rb.x; Bs[nxt][lk + 1][lrow] = rb.y;
            Bs[nxt][lk + 2][lrow] = rb.z; Bs[nxt][lk + 3][lrow] = rb.w;
        }
        __syncthreads();
    }

    #pragma unroll
    for (int m = 0; m < 4; m++) {
        float2 v = make_float2(acc[m][0], acc[m][1]);
        *reinterpret_cast<float2*>(&dst[(row0 + ty * 4 + m) * N + col0 + tx * 2]) = v;
    }
    if (bi != bj) {                   // mirror tile via SMEM transpose
        #pragma unroll
        for (int m = 0; m < 4; m++) {
            Ct[tx * 2 + 0][ty * 4 + m] = acc[m][0];
            Ct[tx * 2 + 1][ty * 4 + m] = acc[m][1];
        }
        __syncthreads();
        #pragma unroll
        for (int idx = tid; idx < 1024; idx += 128) {
            const int r2 = idx >> 5, c2 = idx & 31;
            dst[(col0 + r2) * N + row0 + c2] = Ct[r2][c2];
        }
    }
}

// --- Kernel 2: SmoothAP body, positives-only -------------------------------
// One block per anchor (512 x 256 threads); row assembled from 4 partials.
// Only ~9 of 512 j's per anchor need the k-reduction; jobs striped on warps.
// Tail: single fire-and-forget REDG add into out[0] (no ticket, no fence).
__global__ __launch_bounds__(NT2) void smoothap_kernel(const int* __restrict__ labels,
                                                       float* __restrict__ out) {
    const int i = blockIdx.x;
    const int t = threadIdx.x;

    __shared__ float s[N];       // combined sim row
    __shared__ float pflag[N];   // positive mask
    __shared__ int   jlist[N];   // jlist[0] = i, then positive indices
    __shared__ int   cnt;
    __shared__ float ssum;

    if (t == 0) { cnt = 1; ssum = 0.0f; jlist[0] = i; }
    __syncthreads();

    {   // s[k] = sum of 4 split-K partials (float2-coalesced)
        const int k2 = t * 2;
        float2 v = make_float2(0.f, 0.f);
        #pragma unroll
        for (int q = 0; q < 4; q++) {
            const float2 u = *reinterpret_cast<const float2*>(&d_simP[q][i * N + k2]);
            v.x += u.x; v.y += u.y;
        }
        *reinterpret_cast<float2*>(&s[k2]) = v;
    }

    const int li = labels[i];
    #pragma unroll
    for (int k = t; k < N; k += NT2) {
        const bool p = (labels[k] == li) && (k != i);
        pflag[k] = p ? 1.0f : 0.0f;
        if (p) jlist[atomicAdd(&cnt, 1)] = k;
    }
    __syncthreads();

    const int m1 = cnt;                 // n_pos = m + 1
    const int lane = t & 31, w = t >> 5;

    for (int jj = w; jj < m1; jj += NT2 / 32) {
        const int j = jlist[jj];
        const float sj = s[j];
        float sa = 0.0f, sp = 0.0f;
        #pragma unroll
        for (int it = 0; it < N / 32; it++) {
            const int k = lane + it * 32;
            float g = sig100(s[k] - sj);
            g = (k == j) ? 0.0f : g;    // (1-eye)[j,k] mask
            sa += g;
            sp = fmaf(g, pflag[k], sp);
        }
        #pragma unroll
        for (int o = 16; o; o >>= 1) {
            sa += __shfl_xor_sync(0xFFFFFFFFu, sa, o);
            sp += __shfl_xor_sync(0xFFFFFFFFu, sp, o);
        }
        if (lane == 0) {
            const float ratio = (jj == 0) ? 1.0f / (1.0f + sa)
                                          : (1.0f + sp) / (1.0f + sa);
            atomicAdd(&ssum, ratio);
        }
    }
    __syncthreads();

    // ap contribution: out[0] = 1 - sum_i (ssum_i/m1_i)/N. Fire-and-forget
    // (result unused -> REDG): no ATOMG round-trip, no fence, no ticket.
    if (t == 0 && m1 > 1)
        atomicAdd(out, -(ssum / (float)m1) * (1.0f / (float)N));
}

extern "C" void kernel_launch(void* const* d_in, const int* in_sizes, int n_in,
                              void* d_out, int out_size) {
    const float* preds = (const float*)d_in[0];
    const int* labels = (const int*)d_in[1];
    float* out = (float*)d_out;

    gemm_sym_kernel<<<NGEMM, 128>>>(preds, out);
    smoothap_kernel<<<NB2, NT2>>>(labels, out);
}